// round 1
// baseline (speedup 1.0000x reference)
#include <cuda_runtime.h>
#include <math.h>

// Chamfer distance, B=16, N=M=2048, D=4, fp32.
// dist[b,i,j] = ||x[b,i] - y[b,j] + 1e-12||_2 ; out = sum(min over j) + sum(min over i).
// Strategy: per (batch, direction, query-chunk) block; expansion form
//   ||x-y||^2 = ||y||^2 - 2 x.y + ||x||^2   (||x||^2 added after the min; eps ~1e-12 negligible)
// Database side stored in SMEM as duplicated-packed (-2*p_k, -2*p_k) pairs + (cp, cp),
// so the inner loop is 4 packed fma.rn.f32x2 covering TWO queries at once.

#define BATCH   16
#define NP      2048          // points per set (N == M)
#define THREADS 256
#define XR      2             // queries per thread (one f32x2 packed pair)
#define QB      (THREADS * XR)        // 512 queries per block
#define QCHUNKS (NP / QB)             // 4
#define NBLK    (BATCH * 2 * QCHUNKS) // 128 blocks

__device__ float g_partials[NBLK];

// ---- packed f32x2 helpers -------------------------------------------------
__device__ __forceinline__ unsigned long long pk2(float lo, float hi) {
    unsigned long long r;
    asm("mov.b64 %0, {%1, %2};" : "=l"(r) : "f"(lo), "f"(hi));
    return r;
}
__device__ __forceinline__ void upk2(unsigned long long v, float& lo, float& hi) {
    asm("mov.b64 {%0, %1}, %2;" : "=f"(lo), "=f"(hi) : "l"(v));
}
__device__ __forceinline__ unsigned long long fma2(unsigned long long a,
                                                   unsigned long long b,
                                                   unsigned long long c) {
    unsigned long long d;
    asm("fma.rn.f32x2 %0, %1, %2, %3;" : "=l"(d) : "l"(a), "l"(b), "l"(c));
    return d;
}

// ---- main kernel ----------------------------------------------------------
// grid = NBLK, block = THREADS, dynamic smem = NP * 40 bytes (80 KB)
extern "C" __global__ void __launch_bounds__(THREADS)
chamfer_main(const float* __restrict__ x, const float* __restrict__ y)
{
    const int bid = blockIdx.x;
    const int qc  = bid & (QCHUNKS - 1);        // query chunk
    const int dir = (bid >> 2) & 1;             // 0: queries=x, db=y ; 1: swapped
    const int b   = bid >> 3;                   // batch

    const float* qbase = (dir == 0 ? x : y) + (size_t)b * NP * 4;
    const float* pbase = (dir == 0 ? y : x) + (size_t)b * NP * 4;

    extern __shared__ char smraw[];
    float4* arrA = (float4*)smraw;              // (-2p0,-2p0,-2p1,-2p1)  32 KB
    float4* arrB = arrA + NP;                   // (-2p2,-2p2,-2p3,-2p3)  32 KB
    float2* arrC = (float2*)(arrB + NP);        // (cp, cp)               16 KB

    const int tid = threadIdx.x;

    // cooperative load + transform of the database (coalesced float4 reads)
    for (int j = tid; j < NP; j += THREADS) {
        float4 p = ((const float4*)pbase)[j];
        float cp = p.x * p.x + p.y * p.y + p.z * p.z + p.w * p.w;
        arrA[j] = make_float4(-2.f * p.x, -2.f * p.x, -2.f * p.y, -2.f * p.y);
        arrB[j] = make_float4(-2.f * p.z, -2.f * p.z, -2.f * p.w, -2.f * p.w);
        arrC[j] = make_float2(cp, cp);
    }
    __syncthreads();

    // two queries per thread, packed into lanes of f32x2
    const int q0 = qc * QB + tid;
    const int q1 = q0 + THREADS;
    float4 qa = ((const float4*)qbase)[q0];
    float4 qb = ((const float4*)qbase)[q1];
    unsigned long long a0 = pk2(qa.x, qb.x);
    unsigned long long a1 = pk2(qa.y, qb.y);
    unsigned long long a2 = pk2(qa.z, qb.z);
    unsigned long long a3 = pk2(qa.w, qb.w);
    const float cq0 = qa.x * qa.x + qa.y * qa.y + qa.z * qa.z + qa.w * qa.w;
    const float cq1 = qb.x * qb.x + qb.y * qb.y + qb.z * qb.z + qb.w * qb.w;

    float m0 = 3.402823466e38f;
    float m1 = 3.402823466e38f;

    const ulonglong2* A = (const ulonglong2*)arrA;
    const ulonglong2* B = (const ulonglong2*)arrB;
    const unsigned long long* C = (const unsigned long long*)arrC;

#pragma unroll 8
    for (int j = 0; j < NP; j++) {
        ulonglong2 va = A[j];               // LDS.128, broadcast (same addr all lanes)
        ulonglong2 vb = B[j];               // LDS.128
        unsigned long long vc = C[j];       // LDS.64
        unsigned long long s = fma2(va.x, a0, vc);
        s = fma2(va.y, a1, s);
        s = fma2(vb.x, a2, s);
        s = fma2(vb.y, a3, s);
        float s0, s1;
        upk2(s, s0, s1);
        m0 = fminf(m0, s0);                 // FMNMX -> alu pipe, overlaps FMA pipe
        m1 = fminf(m1, s1);
    }

    float d0 = sqrtf(fmaxf(m0 + cq0, 0.f));
    float d1 = sqrtf(fmaxf(m1 + cq1, 0.f));
    float v = d0 + d1;

    // deterministic block tree-reduce
    __shared__ float red[THREADS];
    red[tid] = v;
    __syncthreads();
#pragma unroll
    for (int s = THREADS / 2; s > 0; s >>= 1) {
        if (tid < s) red[tid] += red[tid + s];
        __syncthreads();
    }
    if (tid == 0) g_partials[bid] = red[0];
}

// ---- final combine --------------------------------------------------------
extern "C" __global__ void chamfer_combine(float* __restrict__ out)
{
    __shared__ float red[NBLK];
    int t = threadIdx.x;
    red[t] = g_partials[t];
    __syncthreads();
#pragma unroll
    for (int s = NBLK / 2; s > 0; s >>= 1) {
        if (t < s) red[t] += red[t + s];
        __syncthreads();
    }
    if (t == 0) out[0] = red[0];
}

// ---- launch ---------------------------------------------------------------
extern "C" void kernel_launch(void* const* d_in, const int* in_sizes, int n_in,
                              void* d_out, int out_size)
{
    const float* x = (const float*)d_in[0];
    const float* y = (const float*)d_in[1];
    float* out = (float*)d_out;

    const size_t smem = (size_t)NP * 40;  // 80 KB
    cudaFuncSetAttribute(chamfer_main, cudaFuncAttributeMaxDynamicSharedMemorySize,
                         (int)smem);

    chamfer_main<<<NBLK, THREADS, smem>>>(x, y);
    chamfer_combine<<<1, NBLK>>>(out);
}

// round 2
// speedup vs baseline: 1.7549x; 1.7549x over previous
#include <cuda_runtime.h>
#include <math.h>
#include <float.h>

// Chamfer distance, B=16, N=M=2048, D=4, fp32.
// ||x-y||^2 = cp - 2 p.q + cq (eps 1e-12 negligible at rel tol 1e-3).
// Main kernel: per (batch, dir, query-chunk, point-chunk) block.
//   - 8 queries per thread, packed 2-per-lane into fma.rn.f32x2 operands.
//   - point chunk (256 pts) in SMEM as duplicated-packed (-2p,-2p) + (cp,cp):
//     3 broadcast LDS per j covering 8 query-point pairs per thread.
//   - per-thread running min of s = cp - 2p.q; cq added after the loop.
// Partial mins -> global scratch; combine: min over chunks, sqrt, sum.

#define BATCH    16
#define NP       2048
#define THREADS  128
#define QPT      8                         // queries per thread
#define QB       (THREADS * QPT)           // 1024 queries per block
#define QCHUNKS  (NP / QB)                 // 2
#define PS       8                         // point chunks
#define PTS      (NP / PS)                 // 256 points per chunk
#define NBLK     (BATCH * 2 * QCHUNKS * PS)  // 512 blocks
#define NQTOT    (BATCH * 2 * NP)          // 65536 (b,dir,query) rows
#define C1BLK    64                        // combine1 blocks
#define C1THR    1024

__device__ float g_partmin[NQTOT * PS];    // [b][dir][q][pchunk], 2 MB
__device__ float g_psum[C1BLK];

// ---- packed f32x2 helpers -------------------------------------------------
__device__ __forceinline__ unsigned long long pk2(float lo, float hi) {
    unsigned long long r;
    asm("mov.b64 %0, {%1, %2};" : "=l"(r) : "f"(lo), "f"(hi));
    return r;
}
__device__ __forceinline__ void upk2(unsigned long long v, float& lo, float& hi) {
    asm("mov.b64 {%0, %1}, %2;" : "=f"(lo), "=f"(hi) : "l"(v));
}
__device__ __forceinline__ unsigned long long fma2(unsigned long long a,
                                                   unsigned long long b,
                                                   unsigned long long c) {
    unsigned long long d;
    asm("fma.rn.f32x2 %0, %1, %2, %3;" : "=l"(d) : "l"(a), "l"(b), "l"(c));
    return d;
}

// ---- main kernel ----------------------------------------------------------
extern "C" __global__ void __launch_bounds__(THREADS)
chamfer_main(const float* __restrict__ x, const float* __restrict__ y)
{
    const int bid = blockIdx.x;
    const int pc  = bid & (PS - 1);
    const int qc  = (bid >> 3) & (QCHUNKS - 1);
    const int dir = (bid >> 4) & 1;
    const int b   = bid >> 5;

    const float* qbase = (dir == 0 ? x : y) + (size_t)b * NP * 4;
    const float* pbase = (dir == 0 ? y : x) + (size_t)b * NP * 4;

    __shared__ float4 arrA[PTS];   // (-2p.x,-2p.x,-2p.y,-2p.y)  4 KB
    __shared__ float4 arrB[PTS];   // (-2p.z,-2p.z,-2p.w,-2p.w)  4 KB
    __shared__ float2 arrC[PTS];   // (cp, cp)                   2 KB

    const int tid = threadIdx.x;

    // cooperative load + transform of this point chunk
    for (int j = tid; j < PTS; j += THREADS) {
        float4 p = ((const float4*)pbase)[pc * PTS + j];
        float cp = p.x * p.x + p.y * p.y + p.z * p.z + p.w * p.w;
        arrA[j] = make_float4(-2.f * p.x, -2.f * p.x, -2.f * p.y, -2.f * p.y);
        arrB[j] = make_float4(-2.f * p.z, -2.f * p.z, -2.f * p.w, -2.f * p.w);
        arrC[j] = make_float2(cp, cp);
    }

    // load 8 queries, pack pairwise (i, i+1)
    unsigned long long a0[4], a1[4], a2[4], a3[4];
    float cq[QPT];
    float4 qv[QPT];
#pragma unroll
    for (int i = 0; i < QPT; i++) {
        int q = qc * QB + i * THREADS + tid;
        qv[i] = ((const float4*)qbase)[q];
        cq[i] = qv[i].x * qv[i].x + qv[i].y * qv[i].y
              + qv[i].z * qv[i].z + qv[i].w * qv[i].w;
    }
#pragma unroll
    for (int p = 0; p < 4; p++) {
        a0[p] = pk2(qv[2*p].x, qv[2*p+1].x);
        a1[p] = pk2(qv[2*p].y, qv[2*p+1].y);
        a2[p] = pk2(qv[2*p].z, qv[2*p+1].z);
        a3[p] = pk2(qv[2*p].w, qv[2*p+1].w);
    }

    float m[QPT];
#pragma unroll
    for (int i = 0; i < QPT; i++) m[i] = FLT_MAX;

    __syncthreads();

    const ulonglong2* A = (const ulonglong2*)arrA;
    const ulonglong2* B = (const ulonglong2*)arrB;
    const unsigned long long* C = (const unsigned long long*)arrC;

#pragma unroll 4
    for (int j = 0; j < PTS; j++) {
        ulonglong2 va = A[j];            // broadcast LDS.128
        ulonglong2 vb = B[j];            // broadcast LDS.128
        unsigned long long vc = C[j];    // broadcast LDS.64
#pragma unroll
        for (int p = 0; p < 4; p++) {
            unsigned long long s = fma2(va.x, a0[p], vc);
            s = fma2(va.y, a1[p], s);
            s = fma2(vb.x, a2[p], s);
            s = fma2(vb.y, a3[p], s);
            float s0, s1;
            upk2(s, s0, s1);
            m[2*p]   = fminf(m[2*p],   s0);   // FMNMX -> alu pipe
            m[2*p+1] = fminf(m[2*p+1], s1);
        }
    }

    // store partial mins (+cq folded in; min over chunks is unaffected since
    // cq is identical across chunks for a given query)
#pragma unroll
    for (int i = 0; i < QPT; i++) {
        int q = qc * QB + i * THREADS + tid;
        size_t row = ((size_t)(b * 2 + dir) * NP + q);
        g_partmin[row * PS + pc] = m[i] + cq[i];
    }
}

// ---- combine stage 1: min over point chunks, sqrt, partial sums -----------
extern "C" __global__ void __launch_bounds__(C1THR)
chamfer_combine1()
{
    const int qg = blockIdx.x * C1THR + threadIdx.x;   // 0..65535
    const float4* p4 = (const float4*)&g_partmin[(size_t)qg * PS];
    float4 u = p4[0];
    float4 v = p4[1];
    float mn = fminf(fminf(fminf(u.x, u.y), fminf(u.z, u.w)),
                     fminf(fminf(v.x, v.y), fminf(v.z, v.w)));
    float d = sqrtf(fmaxf(mn, 0.f));

    __shared__ float red[C1THR];
    red[threadIdx.x] = d;
    __syncthreads();
#pragma unroll
    for (int s = C1THR / 2; s > 0; s >>= 1) {
        if (threadIdx.x < s) red[threadIdx.x] += red[threadIdx.x + s];
        __syncthreads();
    }
    if (threadIdx.x == 0) g_psum[blockIdx.x] = red[0];
}

// ---- combine stage 2: final sum -------------------------------------------
extern "C" __global__ void chamfer_combine2(float* __restrict__ out)
{
    __shared__ float red[C1BLK];
    int t = threadIdx.x;
    red[t] = g_psum[t];
    __syncthreads();
#pragma unroll
    for (int s = C1BLK / 2; s > 0; s >>= 1) {
        if (t < s) red[t] += red[t + s];
        __syncthreads();
    }
    if (t == 0) out[0] = red[0];
}

// ---- launch ---------------------------------------------------------------
extern "C" void kernel_launch(void* const* d_in, const int* in_sizes, int n_in,
                              void* d_out, int out_size)
{
    const float* x = (const float*)d_in[0];
    const float* y = (const float*)d_in[1];
    float* out = (float*)d_out;

    chamfer_main<<<NBLK, THREADS>>>(x, y);
    chamfer_combine1<<<C1BLK, C1THR>>>();
    chamfer_combine2<<<1, C1BLK>>>(out);
}

// round 3
// speedup vs baseline: 1.9514x; 1.1120x over previous
#include <cuda_runtime.h>
#include <math.h>
#include <float.h>

// Chamfer distance, B=16, N=M=2048, D=4, fp32.
// ||x-y||^2 = cp - 2 p.q + cq (eps 1e-12 negligible at rel tol 1e-3).
// Main kernel: per (batch, dir, query-chunk, point-chunk) block.
//   - 8 queries per thread, packed 2-per-lane into fma.rn.f32x2 operands.
//   - point chunk (128 pts) in SMEM as duplicated-packed (-2p,-2p) + (cp,cp):
//     3 broadcast LDS per j covering 8 query-point pairs per thread.
// Partial mins -> [PS][NQTOT] scratch (coalesced both sides); single combine
// kernel does min-over-chunks, sqrt, sum with last-block final reduction.

#define BATCH    16
#define NP       2048
#define THREADS  128
#define QPT      8                           // queries per thread
#define QB       (THREADS * QPT)             // 1024 queries per block
#define QCHUNKS  (NP / QB)                   // 2
#define PS       16                          // point chunks
#define PTS      (NP / PS)                   // 128 points per chunk
#define NBLK     (BATCH * 2 * QCHUNKS * PS)  // 1024 blocks
#define NQTOT    (BATCH * 2 * NP)            // 65536 (b,dir,query) rows
#define C1BLK    64
#define C1THR    1024

__device__ float g_partmin[PS * NQTOT];      // [pchunk][row], 4 MB
__device__ float g_psum[C1BLK];
__device__ unsigned int g_count;             // zero-init; self-resetting

// ---- packed f32x2 helpers -------------------------------------------------
__device__ __forceinline__ unsigned long long pk2(float lo, float hi) {
    unsigned long long r;
    asm("mov.b64 %0, {%1, %2};" : "=l"(r) : "f"(lo), "f"(hi));
    return r;
}
__device__ __forceinline__ void upk2(unsigned long long v, float& lo, float& hi) {
    asm("mov.b64 {%0, %1}, %2;" : "=f"(lo), "=f"(hi) : "l"(v));
}
__device__ __forceinline__ unsigned long long fma2(unsigned long long a,
                                                   unsigned long long b,
                                                   unsigned long long c) {
    unsigned long long d;
    asm("fma.rn.f32x2 %0, %1, %2, %3;" : "=l"(d) : "l"(a), "l"(b), "l"(c));
    return d;
}

// ---- main kernel ----------------------------------------------------------
extern "C" __global__ void __launch_bounds__(THREADS)
chamfer_main(const float* __restrict__ x, const float* __restrict__ y)
{
    const int bid = blockIdx.x;
    const int pc  = bid & (PS - 1);
    const int qc  = (bid >> 4) & (QCHUNKS - 1);
    const int dir = (bid >> 5) & 1;
    const int b   = bid >> 6;

    const float* qbase = (dir == 0 ? x : y) + (size_t)b * NP * 4;
    const float* pbase = (dir == 0 ? y : x) + (size_t)b * NP * 4;

    __shared__ float4 arrA[PTS];   // (-2p.x,-2p.x,-2p.y,-2p.y)
    __shared__ float4 arrB[PTS];   // (-2p.z,-2p.z,-2p.w,-2p.w)
    __shared__ float2 arrC[PTS];   // (cp, cp)

    const int tid = threadIdx.x;

    // cooperative load + transform of this point chunk
    if (tid < PTS) {
        float4 p = ((const float4*)pbase)[pc * PTS + tid];
        float cp = p.x * p.x + p.y * p.y + p.z * p.z + p.w * p.w;
        arrA[tid] = make_float4(-2.f * p.x, -2.f * p.x, -2.f * p.y, -2.f * p.y);
        arrB[tid] = make_float4(-2.f * p.z, -2.f * p.z, -2.f * p.w, -2.f * p.w);
        arrC[tid] = make_float2(cp, cp);
    }

    // load 8 queries, pack pairwise (2i, 2i+1)
    unsigned long long a0[4], a1[4], a2[4], a3[4];
    float cq[QPT];
    float4 qv[QPT];
#pragma unroll
    for (int i = 0; i < QPT; i++) {
        int q = qc * QB + i * THREADS + tid;
        qv[i] = ((const float4*)qbase)[q];
        cq[i] = qv[i].x * qv[i].x + qv[i].y * qv[i].y
              + qv[i].z * qv[i].z + qv[i].w * qv[i].w;
    }
#pragma unroll
    for (int p = 0; p < 4; p++) {
        a0[p] = pk2(qv[2*p].x, qv[2*p+1].x);
        a1[p] = pk2(qv[2*p].y, qv[2*p+1].y);
        a2[p] = pk2(qv[2*p].z, qv[2*p+1].z);
        a3[p] = pk2(qv[2*p].w, qv[2*p+1].w);
    }

    float m[QPT];
#pragma unroll
    for (int i = 0; i < QPT; i++) m[i] = FLT_MAX;

    __syncthreads();

    const ulonglong2* A = (const ulonglong2*)arrA;
    const ulonglong2* B = (const ulonglong2*)arrB;
    const unsigned long long* C = (const unsigned long long*)arrC;

#pragma unroll 4
    for (int j = 0; j < PTS; j++) {
        ulonglong2 va = A[j];            // broadcast LDS.128
        ulonglong2 vb = B[j];            // broadcast LDS.128
        unsigned long long vc = C[j];    // broadcast LDS.64
#pragma unroll
        for (int p = 0; p < 4; p++) {
            unsigned long long s = fma2(va.x, a0[p], vc);
            s = fma2(va.y, a1[p], s);
            s = fma2(vb.x, a2[p], s);
            s = fma2(vb.y, a3[p], s);
            float s0, s1;
            upk2(s, s0, s1);
            m[2*p]   = fminf(m[2*p],   s0);   // FMNMX -> alu pipe
            m[2*p+1] = fminf(m[2*p+1], s1);
        }
    }

    // coalesced partial-min store: layout [pc][row]
#pragma unroll
    for (int i = 0; i < QPT; i++) {
        int q = qc * QB + i * THREADS + tid;
        int row = (b * 2 + dir) * NP + q;
        g_partmin[(size_t)pc * NQTOT + row] = m[i] + cq[i];
    }
}

// ---- combine: min over chunks, sqrt, sum; last block finishes -------------
extern "C" __global__ void __launch_bounds__(C1THR)
chamfer_combine(float* __restrict__ out)
{
    const int qg = blockIdx.x * C1THR + threadIdx.x;   // 0..65535
    float mn = FLT_MAX;
#pragma unroll
    for (int pc = 0; pc < PS; pc++)
        mn = fminf(mn, g_partmin[(size_t)pc * NQTOT + qg]);  // coalesced LDG
    float d = sqrtf(fmaxf(mn, 0.f));

    __shared__ float red[C1THR];
    red[threadIdx.x] = d;
    __syncthreads();
#pragma unroll
    for (int s = C1THR / 2; s > 0; s >>= 1) {
        if (threadIdx.x < s) red[threadIdx.x] += red[threadIdx.x + s];
        __syncthreads();
    }

    __shared__ int is_last;
    if (threadIdx.x == 0) {
        g_psum[blockIdx.x] = red[0];
        __threadfence();
        unsigned int v = atomicAdd(&g_count, 1u);
        is_last = (v == C1BLK - 1);
    }
    __syncthreads();

    if (is_last && threadIdx.x == 0) {
        float t = 0.f;
#pragma unroll
        for (int i = 0; i < C1BLK; i++) t += g_psum[i];  // fixed order: deterministic
        out[0] = t;
        __threadfence();
        g_count = 0;                                     // reset for graph replay
    }
}

// ---- launch ---------------------------------------------------------------
extern "C" void kernel_launch(void* const* d_in, const int* in_sizes, int n_in,
                              void* d_out, int out_size)
{
    const float* x = (const float*)d_in[0];
    const float* y = (const float*)d_in[1];
    float* out = (float*)d_out;

    chamfer_main<<<NBLK, THREADS>>>(x, y);
    chamfer_combine<<<C1BLK, C1THR>>>(out);
}